// round 10
// baseline (speedup 1.0000x reference)
#include <cuda_runtime.h>
#include <cstdint>

#define NN 8192
#define KDIM 512
#define F 64
#define G1_BLOCKS 256
#define BN 72                 // 64 z-cols + 1 ones-col + 7 zero pad
#define KC 64                 // k per pipeline stage
#define ITERS 64              // 4096 / KC per K-half
#define NS 3                  // pipeline stages
#define APITCH 68             // floats per A smem row (64 + 4 pad)
#define BPITCH 68
#define ASZ (128 * APITCH * 4)          // 34816 B
#define BSZ (BN * BPITCH * 4)           // 19584 B
#define SB_OFF (NS * ASZ)
#define MMA_SMEM (NS * (ASZ + BSZ))     // 163200 B

// ---- scratch (static; no allocations) ----
__device__ float        g_z[NN * F];
__device__ float        g_zi[NN];
__device__ float        g_zj[NN];
__device__ float        g_S[F];
__device__ float        g_Spart[G1_BLOCKS * F];
__device__ unsigned int g_cnt_g1;                 // zero-init, self-resetting
__device__ float        g_B[BN * NN];             // rows 0-63: z^T, 64: ones, 65-71 zero (never written)
__device__ float        g_Tp[2 * NN * BN];        // K-split partials of adj@[z|1]

__device__ __forceinline__ uint32_t smem_u32(const void* p) {
    uint32_t a;
    asm("{ .reg .u64 t; cvta.to.shared.u64 t, %1; cvt.u32.u64 %0, t; }" : "=r"(a) : "l"(p));
    return a;
}

#define MMA_TF32(d, a, b0, b1)                                               \
    asm volatile("mma.sync.aligned.m16n8k8.row.col.f32.tf32.tf32.f32 "      \
        "{%0,%1,%2,%3}, {%4,%5,%6,%7}, {%8,%9}, {%0,%1,%2,%3};"             \
        : "+f"((d)[0]), "+f"((d)[1]), "+f"((d)[2]), "+f"((d)[3])            \
        : "r"((a)[0]), "r"((a)[1]), "r"((a)[2]), "r"((a)[3]),               \
          "r"(b0), "r"(b1))

// ===========================================================================
// K0: GEMM z = X W^T + b; epilogue: zi/zj, colsum S, z and z^T (g_B), ones row.
// ===========================================================================
__global__ void __launch_bounds__(256) gemm1_kernel(
    const float* __restrict__ X, const float* __restrict__ W,
    const float* __restrict__ bias,
    const float* __restrict__ a1, const float* __restrict__ a2)
{
    cudaTriggerProgrammaticLaunchCompletion();

    __shared__ float Xs[32][36];
    __shared__ float Ws[32][68];
    __shared__ float sS[64];
    __shared__ int   s_last;

    const int t  = threadIdx.x;
    const int tx = t & 15;
    const int ty = t >> 4;
    const int row0 = blockIdx.x * 32;

    float acc[2][4] = {};
    const float4* X4 = (const float4*)X;
    const float4* W4 = (const float4*)W;

    for (int kc = 0; kc < KDIM; kc += 32) {
        __syncthreads();
        {
            int r = t >> 3, q = t & 7;
            float4 v = X4[(size_t)(row0 + r) * (KDIM / 4) + (kc >> 2) + q];
            *(float4*)&Xs[r][q * 4] = v;
        }
        #pragma unroll
        for (int p = 0; p < 2; p++) {
            int idx = t + p * 256;
            int o = idx >> 3, kq = idx & 7;
            float4 v = W4[o * (KDIM / 4) + (kc >> 2) + kq];
            Ws[kq * 4 + 0][o] = v.x;
            Ws[kq * 4 + 1][o] = v.y;
            Ws[kq * 4 + 2][o] = v.z;
            Ws[kq * 4 + 3][o] = v.w;
        }
        __syncthreads();

        #pragma unroll
        for (int k = 0; k < 32; k++) {
            float4 w = *(const float4*)&Ws[k][tx * 4];
            float x0 = Xs[ty * 2 + 0][k];
            float x1 = Xs[ty * 2 + 1][k];
            acc[0][0] += x0 * w.x; acc[0][1] += x0 * w.y; acc[0][2] += x0 * w.z; acc[0][3] += x0 * w.w;
            acc[1][0] += x1 * w.x; acc[1][1] += x1 * w.y; acc[1][2] += x1 * w.z; acc[1][3] += x1 * w.w;
        }
    }

    float4 bv = ((const float4*)bias)[tx];
    #pragma unroll
    for (int r = 0; r < 2; r++) {
        acc[r][0] += bv.x; acc[r][1] += bv.y; acc[r][2] += bv.z; acc[r][3] += bv.w;
    }

    float4 a1v = ((const float4*)a1)[tx];
    float4 a2v = ((const float4*)a2)[tx];

    #pragma unroll
    for (int r = 0; r < 2; r++) {
        int row = row0 + ty * 2 + r;
        float4 zr;
        zr.x = acc[r][0]; zr.y = acc[r][1]; zr.z = acc[r][2]; zr.w = acc[r][3];
        ((float4*)g_z)[row * 16 + tx] = zr;

        float pzi = a1v.x * zr.x + a1v.y * zr.y + a1v.z * zr.z + a1v.w * zr.w;
        float pzj = a2v.x * zr.x + a2v.y * zr.y + a2v.z * zr.z + a2v.w * zr.w;
        #pragma unroll
        for (int m = 8; m > 0; m >>= 1) {
            pzi += __shfl_xor_sync(0xffffffffu, pzi, m, 16);
            pzj += __shfl_xor_sync(0xffffffffu, pzj, m, 16);
        }
        if (tx == 0) { g_zi[row] = pzi; g_zj[row] = pzj; }
    }

    // z^T into g_B rows 0-63 via smem (reuse Ws: 2176 floats >= 64*33)
    __syncthreads();
    {
        float* sT = &Ws[0][0];
        #pragma unroll
        for (int r = 0; r < 2; r++) {
            int rl = ty * 2 + r;
            sT[(tx*4+0)*33 + rl] = acc[r][0];
            sT[(tx*4+1)*33 + rl] = acc[r][1];
            sT[(tx*4+2)*33 + rl] = acc[r][2];
            sT[(tx*4+3)*33 + rl] = acc[r][3];
        }
        __syncthreads();
        #pragma unroll
        for (int p = 0; p < 8; p++) {
            int idx = t + p * 256;
            int c = idx >> 5, r = idx & 31;
            g_B[c * NN + row0 + r] = sT[c*33 + r];
        }
    }
    if (blockIdx.x < 32) g_B[64 * NN + blockIdx.x * 256 + t] = 1.0f;

    __syncthreads();
    if (t < 64) sS[t] = 0.0f;
    __syncthreads();
    #pragma unroll
    for (int c = 0; c < 4; c++) atomicAdd(&sS[tx * 4 + c], acc[0][c] + acc[1][c]);
    __syncthreads();
    if (t < 64) g_Spart[blockIdx.x * 64 + t] = sS[t];

    __threadfence();
    if (t == 0) {
        unsigned int old = atomicAdd(&g_cnt_g1, 1u);
        s_last = (old == G1_BLOCKS - 1) ? 1 : 0;
        if (s_last) g_cnt_g1 = 0u;
    }
    __syncthreads();
    if (s_last && t < 64) {
        float s = 0.0f;
        #pragma unroll 8
        for (int b = 0; b < G1_BLOCKS; b++) s += __ldcg(&g_Spart[b * 64 + t]);
        g_S[t] = s;
    }
}

// ===========================================================================
// K1: Tp[kh] = adj[:, half] @ B[:, half]^T via mma.sync tf32 (HMMA).
// 128 CTAs = 64 M-tiles x 2 K-halves. cp.async 3-stage pipeline.
// Warp tiling: 4 M-strips(32) x 2 k-split; smem reduce; PDL overlap of
// adj prefetch with gemm1.
// ===========================================================================
__global__ void __launch_bounds__(256) mma_kernel(const float* __restrict__ adj)
{
    extern __shared__ __align__(16) char smem[];
    const uint32_t smb = smem_u32(smem);
    cudaTriggerProgrammaticLaunchCompletion();

    const int tid  = threadIdx.x;
    const int lane = tid & 31;
    const int w    = tid >> 5;
    const int ms   = w & 3;        // M-strip (32 rows)
    const int kw   = w >> 2;       // k-split half

    const int mt    = blockIdx.x >> 1;
    const int kh    = blockIdx.x & 1;
    const int row0  = mt * 128;
    const int kb4   = kh * 1024;   // float4 index base in k

    const float4* adj4 = (const float4*)adj;
    const float4* B4   = (const float4*)g_B;

    // ---- cp.async issuers (no commit) ----
    auto issueA = [&](int c, int s) {
        uint32_t sa = smb + s * ASZ;
        #pragma unroll
        for (int p = 0; p < 8; p++) {
            int idx = tid + p * 256;
            int row = idx >> 4, kq = idx & 15;
            uint32_t so = sa + (uint32_t)(row * APITCH + kq * 4) * 4;
            const float4* g = adj4 + ((size_t)(row0 + row) * 2048 + kb4 + c * 16 + kq);
            asm volatile("cp.async.cg.shared.global [%0], [%1], 16;" :: "r"(so), "l"(g));
        }
    };
    auto issueB = [&](int c, int s) {
        uint32_t sb = smb + SB_OFF + s * BSZ;
        for (int idx = tid; idx < BN * 16; idx += 256) {
            int n = idx >> 4, kq = idx & 15;
            uint32_t so = sb + (uint32_t)(n * BPITCH + kq * 4) * 4;
            const float4* g = B4 + ((size_t)n * 2048 + kb4 + c * 16 + kq);
            asm volatile("cp.async.cg.shared.global [%0], [%1], 16;" :: "r"(so), "l"(g));
        }
    };

    // ---- prologue: adj prefetch BEFORE waiting on gemm1 (PDL overlap) ----
    #pragma unroll
    for (int s = 0; s < NS; s++) {
        issueA(s, s);
        asm volatile("cp.async.commit_group;" ::: "memory");
    }
    cudaGridDependencySynchronize();      // g_B now valid
    #pragma unroll
    for (int s = 0; s < NS; s++) {
        issueB(s, s);
        asm volatile("cp.async.commit_group;" ::: "memory");
    }

    // ---- per-lane ldmatrix address offsets ----
    const uint32_t aoff = (uint32_t)(((ms * 32 + (lane & 15)) * APITCH + ((lane >> 4) * 4)) * 4);
    const uint32_t boff = (uint32_t)(((((lane >> 4) & 1) * 8 + (lane & 7)) * BPITCH
                                      + (((lane >> 3) & 1) * 4)) * 4);
    const uint32_t boff2 = (uint32_t)(((64 + (lane & 7)) * BPITCH + (((lane >> 4) & 1) * 4)) * 4);

    float d[2][9][4];
    #pragma unroll
    for (int mi = 0; mi < 2; mi++)
        #pragma unroll
        for (int n = 0; n < 9; n++)
            #pragma unroll
            for (int e = 0; e < 4; e++) d[mi][n][e] = 0.0f;

    for (int c = 0; c < ITERS; c++) {
        if (c < ITERS - 2)       asm volatile("cp.async.wait_group 2;" ::: "memory");
        else if (c == ITERS - 2) asm volatile("cp.async.wait_group 1;" ::: "memory");
        else                     asm volatile("cp.async.wait_group 0;" ::: "memory");
        __syncthreads();

        const int s = c % NS;
        const uint32_t sa = smb + s * ASZ;
        const uint32_t sb = smb + SB_OFF + s * BSZ;

        #pragma unroll
        for (int t8 = 0; t8 < 4; t8++) {
            const uint32_t k0b = (uint32_t)((kw * 32 + t8 * 8) * 4);
            uint32_t a0[4], a1[4];
            asm volatile("ldmatrix.sync.aligned.m8n8.x4.shared.b16 {%0,%1,%2,%3}, [%4];"
                : "=r"(a0[0]), "=r"(a0[1]), "=r"(a0[2]), "=r"(a0[3])
                : "r"(sa + aoff + k0b));
            asm volatile("ldmatrix.sync.aligned.m8n8.x4.shared.b16 {%0,%1,%2,%3}, [%4];"
                : "=r"(a1[0]), "=r"(a1[1]), "=r"(a1[2]), "=r"(a1[3])
                : "r"(sa + aoff + (uint32_t)(16 * APITCH * 4) + k0b));

            #pragma unroll
            for (int jp = 0; jp < 4; jp++) {
                uint32_t b[4];
                asm volatile("ldmatrix.sync.aligned.m8n8.x4.shared.b16 {%0,%1,%2,%3}, [%4];"
                    : "=r"(b[0]), "=r"(b[1]), "=r"(b[2]), "=r"(b[3])
                    : "r"(sb + boff + (uint32_t)(jp * 16 * BPITCH * 4) + k0b));
                MMA_TF32(d[0][2*jp    ], a0, b[0], b[1]);
                MMA_TF32(d[1][2*jp    ], a1, b[0], b[1]);
                MMA_TF32(d[0][2*jp + 1], a0, b[2], b[3]);
                MMA_TF32(d[1][2*jp + 1], a1, b[2], b[3]);
            }
            {
                uint32_t b8[2];
                asm volatile("ldmatrix.sync.aligned.m8n8.x2.shared.b16 {%0,%1}, [%2];"
                    : "=r"(b8[0]), "=r"(b8[1])
                    : "r"(sb + boff2 + k0b));
                MMA_TF32(d[0][8], a0, b8[0], b8[1]);
                MMA_TF32(d[1][8], a1, b8[0], b8[1]);
            }
        }
        __syncthreads();

        if (c + NS < ITERS) {
            issueA(c + NS, s);
            issueB(c + NS, s);
            asm volatile("cp.async.commit_group;" ::: "memory");
        }
    }

    // ---- k-split reduction via smem, then write g_Tp ----
    __syncthreads();
    float* red = (float*)smem;          // [128 rows][76]
    const int RP = 76;
    const int rbase = ms * 32 + (lane >> 2);
    const int cbase = 2 * (lane & 3);

    if (kw == 1) {
        #pragma unroll
        for (int mi = 0; mi < 2; mi++)
            #pragma unroll
            for (int n = 0; n < 9; n++) {
                int r = rbase + mi * 16;
                int col = n * 8 + cbase;
                *(float2*)&red[r * RP + col]       = make_float2(d[mi][n][0], d[mi][n][1]);
                *(float2*)&red[(r + 8) * RP + col] = make_float2(d[mi][n][2], d[mi][n][3]);
            }
    }
    __syncthreads();
    if (kw == 0) {
        float* out = g_Tp + ((size_t)kh * NN + row0) * BN;
        #pragma unroll
        for (int mi = 0; mi < 2; mi++)
            #pragma unroll
            for (int n = 0; n < 9; n++) {
                int r = rbase + mi * 16;
                int col = n * 8 + cbase;
                float2 p0 = *(float2*)&red[r * RP + col];
                float2 p1 = *(float2*)&red[(r + 8) * RP + col];
                *(float2*)&out[(size_t)r * BN + col] =
                    make_float2(d[mi][n][0] + p0.x, d[mi][n][1] + p0.y);
                *(float2*)&out[(size_t)(r + 8) * BN + col] =
                    make_float2(d[mi][n][2] + p1.x, d[mi][n][3] + p1.y);
            }
    }
}

// ===========================================================================
// K2: finalize. attn@z = (S + (e1-1)*T_full + diag*(e2-e1)*z_i) / D
// ===========================================================================
__global__ void __launch_bounds__(256) finalize_kernel(
    const float* __restrict__ adj, float* __restrict__ out)
{
    cudaGridDependencySynchronize();

    const int t = threadIdx.x;
    const int f = t & 63;
    const int r = t >> 6;
    const int i = blockIdx.x * 4 + r;

    const float* tp0 = g_Tp + (size_t)i * BN;
    const float* tp1 = g_Tp + (size_t)(NN + i) * BN;
    float T    = tp0[f] + tp1[f];
    float deg  = tp0[64] + tp1[64];
    float df   = __ldg(&adj[(size_t)i * NN + i]);
    int   diag = (df != 0.0f);
    int   cnt  = (int)(deg + 0.5f) - diag;

    float zif = g_z[i * 64 + f];
    float zi  = g_zi[i];
    float zj  = g_zj[i];

    float v1 = zi > 0.0f ? zi : 0.01f * zi;
    float e1 = expf(v1);
    float e2 = 0.0f;
    if (diag) {
        float v2 = zi + zj;
        v2 = v2 > 0.0f ? v2 : 0.01f * v2;
        e2 = expf(v2);
    }
    float D   = (float)(NN - cnt - diag) + (float)cnt * e1 + (diag ? e2 : 0.0f);
    float num = g_S[f] + (e1 - 1.0f) * T + (diag ? (e2 - e1) * zif : 0.0f);
    float h   = zif - num / D;
    out[i * 64 + f] = h > 0.0f ? h : 0.0f;
}

// ---------------------------------------------------------------------------
extern "C" void kernel_launch(void* const* d_in, const int* in_sizes, int n_in,
                              void* d_out, int out_size) {
    const float* X   = (const float*)d_in[0];  // (8192, 512)
    const float* adj = (const float*)d_in[1];  // (8192, 8192)
    // d_in[2] = eye_matrix — unused (identity known analytically)
    const float* W   = (const float*)d_in[3];  // (64, 512)
    const float* b   = (const float*)d_in[4];  // (64,)
    const float* a1  = (const float*)d_in[5];  // (1, 64)
    const float* a2  = (const float*)d_in[6];  // (1, 64)
    float* out = (float*)d_out;                // (8192, 64)

    cudaFuncSetAttribute(mma_kernel, cudaFuncAttributeMaxDynamicSharedMemorySize, MMA_SMEM);

    gemm1_kernel<<<G1_BLOCKS, 256>>>(X, W, b, a1, a2);

    cudaLaunchAttribute attrs[1];
    attrs[0].id = cudaLaunchAttributeProgrammaticStreamSerialization;
    attrs[0].val.programmaticStreamSerializationAllowed = 1;

    cudaLaunchConfig_t cfg = {};
    cfg.gridDim  = dim3(128, 1, 1);
    cfg.blockDim = dim3(256, 1, 1);
    cfg.dynamicSmemBytes = MMA_SMEM;
    cfg.stream = 0;
    cfg.attrs = attrs;
    cfg.numAttrs = 1;
    cudaLaunchKernelEx(&cfg, mma_kernel, adj);

    cudaLaunchConfig_t cfg2 = {};
    cfg2.gridDim  = dim3(NN / 4, 1, 1);
    cfg2.blockDim = dim3(256, 1, 1);
    cfg2.dynamicSmemBytes = 0;
    cfg2.stream = 0;
    cfg2.attrs = attrs;
    cfg2.numAttrs = 1;
    cudaLaunchKernelEx(&cfg2, finalize_kernel, adj, out);
}

// round 11
// speedup vs baseline: 1.0245x; 1.0245x over previous
#include <cuda_runtime.h>
#include <cstdint>

#define NN 8192
#define KDIM 512
#define F 64
#define G1_BLOCKS 128
#define BN 80                 // 64 z-cols + 1 ones-col + 15 zero pad
#define PITCH 68              // floats per smem tile row (64 + 4 pad)
#define NS 3
#define ITERS 64              // 4096 / 64 per K-half
#define ASZb (128 * PITCH * 4)       // 34816
#define BSZb (BN * PITCH * 4)        // 21760
#define STG  (ASZb + BSZb)           // 56576
#define MB_OFF (NS * STG)            // 169728
#define MMA_SMEM (MB_OFF + 64)
#define TX_BYTES ((128 + BN) * 256)  // 53248

// ---- scratch (static; no allocations) ----
__device__ float        g_z[NN * F];
__device__ float        g_zi[NN];
__device__ float        g_zj[NN];
__device__ float        g_S[F];
__device__ float        g_Spart[G1_BLOCKS * F];
__device__ unsigned int g_cnt_g1;                 // zero-init, self-resetting
__device__ float        g_B[BN * NN];             // rows 0-63: z^T, row 64: ones, 65-79: zero
__device__ float        g_Tp[2 * NN * BN];        // K-split partials of adj@[z|1|0pad]

__device__ __forceinline__ uint32_t smem_u32(const void* p) {
    uint32_t a;
    asm("{ .reg .u64 t; cvta.to.shared.u64 t, %1; cvt.u32.u64 %0, t; }" : "=r"(a) : "l"(p));
    return a;
}

#define MBARRIER_INIT(addr, cnt) \
    asm volatile("mbarrier.init.shared.b64 [%0], %1;" :: "r"(addr), "r"((uint32_t)(cnt)) : "memory")
#define MBARRIER_EXPECT_TX(addr, bytes) \
    asm volatile("mbarrier.arrive.expect_tx.shared.b64 _, [%0], %1;" :: "r"(addr), "r"((uint32_t)(bytes)) : "memory")
#define MBARRIER_WAIT_PARITY(addr, par) do {                                        \
    uint32_t _a = (addr); uint32_t _p = (uint32_t)(par); uint32_t _d;               \
    asm volatile("{\n\t.reg .pred p;\n\t"                                           \
        "mbarrier.try_wait.parity.acquire.cta.shared::cta.b64 p, [%1], %2;\n\t"     \
        "selp.b32 %0, 1, 0, p;\n\t}" : "=r"(_d) : "r"(_a), "r"(_p) : "memory");     \
    if (!_d) {                                                                      \
        asm volatile("{\n\t.reg .pred P1;\n\t"                                      \
            "WL_%=:\n\t"                                                            \
            "mbarrier.try_wait.parity.acquire.cta.shared::cta.b64 P1, [%0], %1, 0x989680;\n\t" \
            "@P1 bra.uni WD_%=;\n\tbra.uni WL_%=;\n\tWD_%=:\n\t}"                   \
            :: "r"(_a), "r"(_p) : "memory");                                        \
    }                                                                               \
} while (0)
#define BULK_CP(dst, src, bytes, mbar) \
    asm volatile("cp.async.bulk.shared::cluster.global.mbarrier::complete_tx::bytes [%0], [%1], %2, [%3];" \
                 :: "r"(dst), "l"(src), "r"((uint32_t)(bytes)), "r"(mbar) : "memory")

#define MMA_TF32(d, a, b0, b1)                                               \
    asm volatile("mma.sync.aligned.m16n8k8.row.col.f32.tf32.tf32.f32 "      \
        "{%0,%1,%2,%3}, {%4,%5,%6,%7}, {%8,%9}, {%0,%1,%2,%3};"             \
        : "+f"((d)[0]), "+f"((d)[1]), "+f"((d)[2]), "+f"((d)[3])            \
        : "r"((a)[0]), "r"((a)[1]), "r"((a)[2]), "r"((a)[3]),               \
          "r"(b0), "r"(b1))

// ===========================================================================
// K0: GEMM z = X W^T + b (128 blocks x 64 rows, round-6 proven shape);
// epilogue: zi/zj, colsum S, z, z^T -> g_B, ones row. PDL trigger at END.
// ===========================================================================
__global__ void __launch_bounds__(256) gemm1_kernel(
    const float* __restrict__ X, const float* __restrict__ W,
    const float* __restrict__ bias,
    const float* __restrict__ a1, const float* __restrict__ a2)
{
    __shared__ float Xs[64][36];
    __shared__ float Ws[32][68];
    __shared__ float sT[64][65];
    __shared__ float sS[64];
    __shared__ int   s_last;

    const int t  = threadIdx.x;
    const int tx = t & 15;
    const int ty = t >> 4;
    const int row0 = blockIdx.x * 64;

    float acc[4][4] = {};
    const float4* X4 = (const float4*)X;
    const float4* W4 = (const float4*)W;

    for (int kc = 0; kc < KDIM; kc += 32) {
        __syncthreads();
        #pragma unroll
        for (int p = 0; p < 2; p++) {
            int idx = t + p * 256;
            int r = idx >> 3, q = idx & 7;
            float4 v = X4[(size_t)(row0 + r) * (KDIM / 4) + (kc >> 2) + q];
            *(float4*)&Xs[r][q * 4] = v;
        }
        #pragma unroll
        for (int p = 0; p < 2; p++) {
            int idx = t + p * 256;
            int o = idx >> 3, kq = idx & 7;
            float4 v = W4[o * (KDIM / 4) + (kc >> 2) + kq];
            Ws[kq * 4 + 0][o] = v.x;
            Ws[kq * 4 + 1][o] = v.y;
            Ws[kq * 4 + 2][o] = v.z;
            Ws[kq * 4 + 3][o] = v.w;
        }
        __syncthreads();

        #pragma unroll
        for (int k = 0; k < 32; k++) {
            float4 w = *(const float4*)&Ws[k][tx * 4];
            float x0 = Xs[ty * 4 + 0][k];
            float x1 = Xs[ty * 4 + 1][k];
            float x2 = Xs[ty * 4 + 2][k];
            float x3 = Xs[ty * 4 + 3][k];
            acc[0][0] += x0 * w.x; acc[0][1] += x0 * w.y; acc[0][2] += x0 * w.z; acc[0][3] += x0 * w.w;
            acc[1][0] += x1 * w.x; acc[1][1] += x1 * w.y; acc[1][2] += x1 * w.z; acc[1][3] += x1 * w.w;
            acc[2][0] += x2 * w.x; acc[2][1] += x2 * w.y; acc[2][2] += x2 * w.z; acc[2][3] += x2 * w.w;
            acc[3][0] += x3 * w.x; acc[3][1] += x3 * w.y; acc[3][2] += x3 * w.z; acc[3][3] += x3 * w.w;
        }
    }

    float4 bv = ((const float4*)bias)[tx];
    #pragma unroll
    for (int r = 0; r < 4; r++) {
        acc[r][0] += bv.x; acc[r][1] += bv.y; acc[r][2] += bv.z; acc[r][3] += bv.w;
    }

    float4 a1v = ((const float4*)a1)[tx];
    float4 a2v = ((const float4*)a2)[tx];

    #pragma unroll
    for (int r = 0; r < 4; r++) {
        int row = row0 + ty * 4 + r;
        float4 zr;
        zr.x = acc[r][0]; zr.y = acc[r][1]; zr.z = acc[r][2]; zr.w = acc[r][3];
        ((float4*)g_z)[row * 16 + tx] = zr;

        float pzi = a1v.x * zr.x + a1v.y * zr.y + a1v.z * zr.z + a1v.w * zr.w;
        float pzj = a2v.x * zr.x + a2v.y * zr.y + a2v.z * zr.z + a2v.w * zr.w;
        #pragma unroll
        for (int m = 8; m > 0; m >>= 1) {
            pzi += __shfl_xor_sync(0xffffffffu, pzi, m, 16);
            pzj += __shfl_xor_sync(0xffffffffu, pzj, m, 16);
        }
        if (tx == 0) { g_zi[row] = pzi; g_zj[row] = pzj; }
    }

    // ---- z^T into g_B rows 0-63 ----
    __syncthreads();
    #pragma unroll
    for (int r = 0; r < 4; r++) {
        #pragma unroll
        for (int c = 0; c < 4; c++)
            sT[tx * 4 + c][ty * 4 + r] = acc[r][c];
    }
    __syncthreads();
    #pragma unroll
    for (int p = 0; p < 16; p++) {
        int idx = t + p * 256;
        int c = idx >> 6, rl = idx & 63;
        g_B[c * NN + row0 + rl] = sT[c][rl];
    }
    if (t < 64) g_B[64 * NN + row0 + t] = 1.0f;   // ones row

    // ---- column sums ----
    __syncthreads();
    if (t < 64) sS[t] = 0.0f;
    __syncthreads();
    #pragma unroll
    for (int c = 0; c < 4; c++)
        atomicAdd(&sS[tx * 4 + c], acc[0][c] + acc[1][c] + acc[2][c] + acc[3][c]);
    __syncthreads();
    if (t < 64) g_Spart[blockIdx.x * 64 + t] = sS[t];

    __threadfence();
    if (t == 0) {
        unsigned int old = atomicAdd(&g_cnt_g1, 1u);
        s_last = (old == G1_BLOCKS - 1) ? 1 : 0;
        if (s_last) g_cnt_g1 = 0u;
    }
    __syncthreads();
    if (s_last && t < 64) {
        float s = 0.0f;
        #pragma unroll 8
        for (int b = 0; b < G1_BLOCKS; b++) s += __ldcg(&g_Spart[b * 64 + t]);
        g_S[t] = s;
    }
    __syncthreads();
    cudaTriggerProgrammaticLaunchCompletion();   // AFTER all writes (correctness)
}

// ===========================================================================
// K1: Tp[kh] = adj[:, half] @ B[:, half]^T via HMMA tf32.
// 128 CTAs = 64 M-tiles x 2 K-halves, 512 threads.
// cp.async.bulk row copies + mbarrier, 3-stage ring.
// Warp tiling: mh(2) x nh(2) x kw(4): Mw=64, Nw=40, kw=16.
// ===========================================================================
__global__ void __launch_bounds__(512, 1) mma_kernel(const float* __restrict__ adj)
{
    extern __shared__ __align__(16) char smem[];
    const uint32_t smb = smem_u32(smem);

    const int tid  = threadIdx.x;
    const int lane = tid & 31;
    const int w    = tid >> 5;
    const int mh   = w & 1;
    const int nh   = (w >> 1) & 1;
    const int kw   = w >> 2;        // 0..3

    const int mt   = blockIdx.x >> 1;
    const int kh   = blockIdx.x & 1;
    const int row0 = mt * 128;
    const size_t kbase = (size_t)kh * 4096;

    if (tid < NS) MBARRIER_INIT(smb + MB_OFF + 8 * tid, 1);
    __syncthreads();

    const float* Bsrc = g_B;

    // wait for gemm1 (g_B ready), then prefill 3 stages
    cudaGridDependencySynchronize();

    auto fill = [&](int c, int s) {
        // one thread posts the tx expectation FIRST (sync follows at callsite)
        if (tid == 0) MBARRIER_EXPECT_TX(smb + MB_OFF + 8 * s, TX_BYTES);
    };
    auto issue = [&](int c, int s) {
        const uint32_t mb = smb + MB_OFF + 8 * s;
        if (tid < 128) {
            uint32_t dst = smb + s * STG + tid * (PITCH * 4);
            const float* src = adj + ((size_t)(row0 + tid) * NN + kbase + c * 64);
            BULK_CP(dst, src, 256, mb);
        } else if (tid < 128 + BN) {
            int n = tid - 128;
            uint32_t dst = smb + s * STG + ASZb + n * (PITCH * 4);
            const float* src = Bsrc + ((size_t)n * NN + kbase + c * 64);
            BULK_CP(dst, src, 256, mb);
        }
    };

    #pragma unroll
    for (int s = 0; s < NS; s++) {
        fill(s, s);
        __syncthreads();
        issue(s, s);
    }

    // per-lane intra-tile offsets (floats)
    const int arow = (lane & 15) * PITCH + (lane >> 4) * 4;
    const int b4l  = (((lane >> 4) & 1) * 8 + (lane & 7)) * PITCH + ((lane >> 3) & 1) * 4;
    const int b2l  = (lane & 7) * PITCH + ((lane >> 3) & 1) * 4;

    float d[4][5][4];
    #pragma unroll
    for (int mi = 0; mi < 4; mi++)
        #pragma unroll
        for (int nj = 0; nj < 5; nj++)
            #pragma unroll
            for (int e = 0; e < 4; e++) d[mi][nj][e] = 0.0f;

    for (int c = 0; c < ITERS; c++) {
        const int s = c % NS;
        MBARRIER_WAIT_PARITY(smb + MB_OFF + 8 * s, (c / NS) & 1);

        const uint32_t sa = smb + s * STG;
        const uint32_t sb = sa + ASZb;

        #pragma unroll
        for (int k8 = 0; k8 < 2; k8++) {
            const int kcol = kw * 16 + k8 * 8;

            uint32_t b0[4], b1[4], b2[2];
            asm volatile("ldmatrix.sync.aligned.m8n8.x4.shared.b16 {%0,%1,%2,%3}, [%4];"
                : "=r"(b0[0]), "=r"(b0[1]), "=r"(b0[2]), "=r"(b0[3])
                : "r"(sb + (uint32_t)(((nh * 40 + 0) * PITCH + kcol + b4l) * 4)));
            asm volatile("ldmatrix.sync.aligned.m8n8.x4.shared.b16 {%0,%1,%2,%3}, [%4];"
                : "=r"(b1[0]), "=r"(b1[1]), "=r"(b1[2]), "=r"(b1[3])
                : "r"(sb + (uint32_t)(((nh * 40 + 16) * PITCH + kcol + b4l) * 4)));
            asm volatile("ldmatrix.sync.aligned.m8n8.x2.shared.b16 {%0,%1}, [%2];"
                : "=r"(b2[0]), "=r"(b2[1])
                : "r"(sb + (uint32_t)(((nh * 40 + 32) * PITCH + kcol + b2l) * 4)));

            #pragma unroll
            for (int mi = 0; mi < 4; mi++) {
                uint32_t a[4];
                asm volatile("ldmatrix.sync.aligned.m8n8.x4.shared.b16 {%0,%1,%2,%3}, [%4];"
                    : "=r"(a[0]), "=r"(a[1]), "=r"(a[2]), "=r"(a[3])
                    : "r"(sa + (uint32_t)((((mh * 64 + mi * 16) * PITCH) + kcol + arow) * 4)));
                MMA_TF32(d[mi][0], a, b0[0], b0[1]);
                MMA_TF32(d[mi][1], a, b0[2], b0[3]);
                MMA_TF32(d[mi][2], a, b1[0], b1[1]);
                MMA_TF32(d[mi][3], a, b1[2], b1[3]);
                MMA_TF32(d[mi][4], a, b2[0], b2[1]);
            }
        }
        __syncthreads();     // all warps done reading stage s

        if (c + NS < ITERS) {
            fill(c + NS, s);
            __syncthreads(); // expect_tx precedes bulk issues
            issue(c + NS, s);
        }
    }

    // ---- kw-split reduction via smem (stages no longer needed) ----
    __syncthreads();
    float* red = (float*)smem;      // 3 buffers of [128][84]
    const int RP = 84;
    const int fr = lane >> 2;
    const int fc = 2 * (lane & 3);

    if (kw > 0) {
        float* rb = red + (kw - 1) * (128 * RP);
        #pragma unroll
        for (int mi = 0; mi < 4; mi++)
            #pragma unroll
            for (int nj = 0; nj < 5; nj++) {
                int r = mh * 64 + mi * 16 + fr;
                int col = nh * 40 + nj * 8 + fc;
                *(float2*)&rb[r * RP + col]       = make_float2(d[mi][nj][0], d[mi][nj][1]);
                *(float2*)&rb[(r + 8) * RP + col] = make_float2(d[mi][nj][2], d[mi][nj][3]);
            }
    }
    __syncthreads();
    if (kw == 0) {
        float* out = g_Tp + ((size_t)kh * NN + row0) * BN;
        #pragma unroll
        for (int mi = 0; mi < 4; mi++)
            #pragma unroll
            for (int nj = 0; nj < 5; nj++) {
                int r = mh * 64 + mi * 16 + fr;
                int col = nh * 40 + nj * 8 + fc;
                float2 s0 = make_float2(d[mi][nj][0], d[mi][nj][1]);
                float2 s1 = make_float2(d[mi][nj][2], d[mi][nj][3]);
                #pragma unroll
                for (int q = 0; q < 3; q++) {
                    float* rb = red + q * (128 * RP);
                    float2 p0 = *(float2*)&rb[r * RP + col];
                    float2 p1 = *(float2*)&rb[(r + 8) * RP + col];
                    s0.x += p0.x; s0.y += p0.y;
                    s1.x += p1.x; s1.y += p1.y;
                }
                *(float2*)&out[(size_t)r * BN + col]       = s0;
                *(float2*)&out[(size_t)(r + 8) * BN + col] = s1;
            }
    }
}

// ===========================================================================
// K2: finalize. attn@z = (S + (e1-1)*T_full + diag*(e2-e1)*z_i) / D
// ===========================================================================
__global__ void __launch_bounds__(256) finalize_kernel(
    const float* __restrict__ adj, float* __restrict__ out)
{
    cudaGridDependencySynchronize();

    const int t = threadIdx.x;
    const int f = t & 63;
    const int r = t >> 6;
    const int i = blockIdx.x * 4 + r;

    const float* tp0 = g_Tp + (size_t)i * BN;
    const float* tp1 = g_Tp + (size_t)(NN + i) * BN;
    float T    = tp0[f] + tp1[f];
    float deg  = tp0[64] + tp1[64];
    float df   = __ldg(&adj[(size_t)i * NN + i]);
    int   diag = (df != 0.0f);
    int   cnt  = (int)(deg + 0.5f) - diag;

    float zif = g_z[i * 64 + f];
    float zi  = g_zi[i];
    float zj  = g_zj[i];

    float v1 = zi > 0.0f ? zi : 0.01f * zi;
    float e1 = expf(v1);
    float e2 = 0.0f;
    if (diag) {
        float v2 = zi + zj;
        v2 = v2 > 0.0f ? v2 : 0.01f * v2;
        e2 = expf(v2);
    }
    float D   = (float)(NN - cnt - diag) + (float)cnt * e1 + (diag ? e2 : 0.0f);
    float num = g_S[f] + (e1 - 1.0f) * T + (diag ? (e2 - e1) * zif : 0.0f);
    float h   = zif - num / D;
    out[i * 64 + f] = h > 0.0f ? h : 0.0f;
}

// ---------------------------------------------------------------------------
extern "C" void kernel_launch(void* const* d_in, const int* in_sizes, int n_in,
                              void* d_out, int out_size) {
    const float* X   = (const float*)d_in[0];  // (8192, 512)
    const float* adj = (const float*)d_in[1];  // (8192, 8192)
    // d_in[2] = eye_matrix — unused (identity known analytically)
    const float* W   = (const float*)d_in[3];  // (64, 512)
    const float* b   = (const float*)d_in[4];  // (64,)
    const float* a1  = (const float*)d_in[5];  // (1, 64)
    const float* a2  = (const float*)d_in[6];  // (1, 64)
    float* out = (float*)d_out;                // (8192, 64)

    cudaFuncSetAttribute(mma_kernel, cudaFuncAttributeMaxDynamicSharedMemorySize, MMA_SMEM);

    gemm1_kernel<<<G1_BLOCKS, 256>>>(X, W, b, a1, a2);

    cudaLaunchAttribute attrs[1];
    attrs[0].id = cudaLaunchAttributeProgrammaticStreamSerialization;
    attrs[0].val.programmaticStreamSerializationAllowed = 1;

    cudaLaunchConfig_t cfg = {};
    cfg.gridDim  = dim3(128, 1, 1);
    cfg.blockDim = dim3(512, 1, 1);
    cfg.dynamicSmemBytes = MMA_SMEM;
    cfg.stream = 0;
    cfg.attrs = attrs;
    cfg.numAttrs = 1;
    cudaLaunchKernelEx(&cfg, mma_kernel, adj);

    cudaLaunchConfig_t cfg2 = {};
    cfg2.gridDim  = dim3(NN / 4, 1, 1);
    cfg2.blockDim = dim3(256, 1, 1);
    cfg2.dynamicSmemBytes = 0;
    cfg2.stream = 0;
    cfg2.attrs = attrs;
    cfg2.numAttrs = 1;
    cudaLaunchKernelEx(&cfg2, finalize_kernel, adj, out);
}